// round 1
// baseline (speedup 1.0000x reference)
#include <cuda_runtime.h>

#define H_  8
#define D_  512
#define DK_ 64
#define B_  16
#define N_  8192
#define ROWS_ (B_ * N_)

// scratch: scores[b][h][n]  (4 MB)
__device__ float g_scores[B_ * H_ * N_];

typedef unsigned long long u64;

__device__ __forceinline__ u64 ffma2(u64 a, u64 b, u64 c) {
    u64 d;
    asm("fma.rn.f32x2 %0, %1, %2, %3;" : "=l"(d) : "l"(a), "l"(b), "l"(c));
    return d;
}

__device__ __forceinline__ float2 unpack2(u64 v) {
    float lo, hi;
    asm("mov.b64 {%0, %1}, %2;" : "=f"(lo), "=f"(hi) : "l"(v));
    return make_float2(lo, hi);
}

// ---------------------------------------------------------------------------
// Pass 1: per 64-row tile of x, compute K = x@Wk^T, G = x@Wg^T one head (64
// cols) at a time, gate with tanh*sigmoid, dot against query -> scores.
// Inner GEMM loop is packed f32x2 FMA (FFMA2) for 2x fp32 throughput.
// ---------------------------------------------------------------------------
__global__ __launch_bounds__(256, 2)
void pass1_kernel(const float* __restrict__ x,
                  const float* __restrict__ Wk,
                  const float* __restrict__ Wg,
                  const float* __restrict__ q)
{
    __shared__ float2 As[32][64];   // A operand, each value duplicated (a,a): 16 KB
    __shared__ float  Bk[32][64];   // Wk tile, k-major: 8 KB
    __shared__ float  Bg[32][64];   // Wg tile, k-major: 8 KB

    const int tid  = threadIdx.x;
    const int tx   = tid & 15;      // col group (4 cols each)
    const int ty   = tid >> 4;      // row group (4 rows each)
    const int row0 = blockIdx.x * 64;
    const int b    = row0 / N_;     // whole block is one batch (N_ % 64 == 0)
    const int n0   = row0 % N_;

#pragma unroll 1
    for (int h = 0; h < H_; ++h) {
        u64 cK[4][2], cG[4][2];
#pragma unroll
        for (int r = 0; r < 4; ++r)
#pragma unroll
            for (int c = 0; c < 2; ++c) { cK[r][c] = 0ull; cG[r][c] = 0ull; }

        const float* wkh = Wk + (size_t)(h * DK_) * D_;
        const float* wgh = Wg + (size_t)(h * DK_) * D_;

#pragma unroll 1
        for (int kk = 0; kk < D_; kk += 32) {
            __syncthreads();
            // load X tile (64 rows x 32 k), store transposed + duplicated
#pragma unroll
            for (int i = 0; i < 2; ++i) {
                int idx = tid + i * 256;          // 0..511
                int r   = idx >> 3;               // row 0..63
                int kq  = (idx & 7) << 2;         // k 0,4,..,28
                float4 v = *(const float4*)(x + (size_t)(row0 + r) * D_ + kk + kq);
                As[kq + 0][r] = make_float2(v.x, v.x);
                As[kq + 1][r] = make_float2(v.y, v.y);
                As[kq + 2][r] = make_float2(v.z, v.z);
                As[kq + 3][r] = make_float2(v.w, v.w);
            }
            // load Wk / Wg tiles (64 head-cols x 32 k), store k-major
#pragma unroll
            for (int i = 0; i < 2; ++i) {
                int idx = tid + i * 256;
                int r   = idx >> 3;               // head col 0..63
                int kq  = (idx & 7) << 2;
                float4 vk = *(const float4*)(wkh + (size_t)r * D_ + kk + kq);
                Bk[kq + 0][r] = vk.x; Bk[kq + 1][r] = vk.y;
                Bk[kq + 2][r] = vk.z; Bk[kq + 3][r] = vk.w;
                float4 vg = *(const float4*)(wgh + (size_t)r * D_ + kk + kq);
                Bg[kq + 0][r] = vg.x; Bg[kq + 1][r] = vg.y;
                Bg[kq + 2][r] = vg.z; Bg[kq + 3][r] = vg.w;
            }
            __syncthreads();

#pragma unroll
            for (int k = 0; k < 32; ++k) {
                const u64* ap  = (const u64*)&As[k][ty << 2];  // 4 dup'd a (2x LDS.128)
                u64 a0 = ap[0], a1 = ap[1], a2 = ap[2], a3 = ap[3];
                const u64* bkp = (const u64*)&Bk[k][tx << 2];  // 2 col-pairs (LDS.128)
                u64 bk0 = bkp[0], bk1 = bkp[1];
                const u64* bgp = (const u64*)&Bg[k][tx << 2];
                u64 bg0 = bgp[0], bg1 = bgp[1];

                cK[0][0] = ffma2(a0, bk0, cK[0][0]); cK[0][1] = ffma2(a0, bk1, cK[0][1]);
                cK[1][0] = ffma2(a1, bk0, cK[1][0]); cK[1][1] = ffma2(a1, bk1, cK[1][1]);
                cK[2][0] = ffma2(a2, bk0, cK[2][0]); cK[2][1] = ffma2(a2, bk1, cK[2][1]);
                cK[3][0] = ffma2(a3, bk0, cK[3][0]); cK[3][1] = ffma2(a3, bk1, cK[3][1]);

                cG[0][0] = ffma2(a0, bg0, cG[0][0]); cG[0][1] = ffma2(a0, bg1, cG[0][1]);
                cG[1][0] = ffma2(a1, bg0, cG[1][0]); cG[1][1] = ffma2(a1, bg1, cG[1][1]);
                cG[2][0] = ffma2(a2, bg0, cG[2][0]); cG[2][1] = ffma2(a2, bg1, cG[2][1]);
                cG[3][0] = ffma2(a3, bg0, cG[3][0]); cG[3][1] = ffma2(a3, bg1, cG[3][1]);
            }
        }

        // gate + query dot: score[r] = sum_col q[h,col] * tanh(K) * sigmoid(G)
        float rs[4];
#pragma unroll
        for (int r = 0; r < 4; ++r) {
            float s = 0.f;
#pragma unroll
            for (int c = 0; c < 2; ++c) {
                float2 k2 = unpack2(cK[r][c]);
                float2 g2 = unpack2(cG[r][c]);
                int col = (tx << 2) + (c << 1);
                float q0 = q[h * DK_ + col];
                float q1 = q[h * DK_ + col + 1];
                float t0 = tanhf(k2.x) * (1.f / (1.f + __expf(-g2.x)));
                float t1 = tanhf(k2.y) * (1.f / (1.f + __expf(-g2.y)));
                s += q0 * t0 + q1 * t1;
            }
            rs[r] = s;
        }
        // reduce across the 16 tx lanes sharing the same rows (contiguous in warp)
#pragma unroll
        for (int off = 8; off >= 1; off >>= 1) {
#pragma unroll
            for (int r = 0; r < 4; ++r)
                rs[r] += __shfl_xor_sync(0xffffffffu, rs[r], off, 16);
        }
        if (tx == 0) {
#pragma unroll
            for (int r = 0; r < 4; ++r) {
                int n = n0 + (ty << 2) + r;
                g_scores[((size_t)b * H_ + h) * N_ + n] = rs[r];
            }
        }
    }
}

// ---------------------------------------------------------------------------
// Pass 2: per (b,h) block: softmax over 8192 scores, then weighted sum of x.
// ---------------------------------------------------------------------------
__global__ __launch_bounds__(512)
void pass2_kernel(const float* __restrict__ x, float* __restrict__ out)
{
    __shared__ float wbuf[N_];     // 32 KB exp weights
    __shared__ float red[16];
    __shared__ float red2[512];

    const int b   = blockIdx.x >> 3;
    const int h   = blockIdx.x & 7;
    const int tid = threadIdx.x;
    const float* sc = g_scores + ((size_t)b * H_ + h) * N_;

    // --- max ---
    float mx = -1e30f;
    for (int i = tid; i < N_; i += 512) mx = fmaxf(mx, sc[i]);
#pragma unroll
    for (int off = 16; off >= 1; off >>= 1)
        mx = fmaxf(mx, __shfl_xor_sync(0xffffffffu, mx, off));
    if ((tid & 31) == 0) red[tid >> 5] = mx;
    __syncthreads();
    if (tid < 32) {
        float v = (tid < 16) ? red[tid] : -1e30f;
#pragma unroll
        for (int off = 8; off >= 1; off >>= 1)
            v = fmaxf(v, __shfl_xor_sync(0xffffffffu, v, off));
        if (tid == 0) red[0] = v;
    }
    __syncthreads();
    mx = red[0];
    __syncthreads();

    // --- exp + sum ---
    float sum = 0.f;
    for (int i = tid; i < N_; i += 512) {
        float e = __expf(sc[i] - mx);
        wbuf[i] = e;
        sum += e;
    }
#pragma unroll
    for (int off = 16; off >= 1; off >>= 1)
        sum += __shfl_xor_sync(0xffffffffu, sum, off);
    if ((tid & 31) == 0) red[tid >> 5] = sum;
    __syncthreads();
    if (tid < 32) {
        float v = (tid < 16) ? red[tid] : 0.f;
#pragma unroll
        for (int off = 8; off >= 1; off >>= 1)
            v += __shfl_xor_sync(0xffffffffu, v, off);
        if (tid == 0) red[0] = v;
    }
    __syncthreads();
    const float inv = 1.f / red[0];

    // --- weighted sum: out[d] = sum_n w[n] * x[b, n, h*64 + d] ---
    const int d     = tid & 63;
    const int slice = tid >> 6;    // 0..7
    const float* xp = x + (size_t)b * N_ * D_ + h * DK_ + d;

    float a0 = 0.f, a1 = 0.f, a2 = 0.f, a3 = 0.f;
    for (int n = slice; n < N_; n += 32) {
        a0 = fmaf(wbuf[n],      xp[(size_t)(n)      * D_], a0);
        a1 = fmaf(wbuf[n + 8],  xp[(size_t)(n + 8)  * D_], a1);
        a2 = fmaf(wbuf[n + 16], xp[(size_t)(n + 16) * D_], a2);
        a3 = fmaf(wbuf[n + 24], xp[(size_t)(n + 24) * D_], a3);
    }
    red2[tid] = (a0 + a1) + (a2 + a3);
    __syncthreads();
    if (slice == 0) {
        float a = 0.f;
#pragma unroll
        for (int s = 0; s < 8; ++s) a += red2[s * 64 + d];
        out[(size_t)b * D_ + h * DK_ + d] = a * inv;
    }
}

extern "C" void kernel_launch(void* const* d_in, const int* in_sizes, int n_in,
                              void* d_out, int out_size)
{
    const float* x  = (const float*)d_in[0];
    const float* Wk = (const float*)d_in[1];
    const float* Wg = (const float*)d_in[2];
    const float* q  = (const float*)d_in[3];
    float* out = (float*)d_out;

    pass1_kernel<<<ROWS_ / 64, 256>>>(x, Wk, Wg, q);
    pass2_kernel<<<B_ * H_, 512>>>(x, out);
}

// round 3
// speedup vs baseline: 3.7885x; 3.7885x over previous
#include <cuda_runtime.h>
#include <cuda_bf16.h>
#include <cstdint>

#define H_  8
#define D_  512
#define DK_ 64
#define B_  16
#define N_  8192
#define ROWS_ (B_ * N_)

// ---------------- device scratch ---------------------------------------------
__device__ float g_scores[B_ * H_ * N_];                 // scores -> exp weights
__device__ float g_inv[B_ * H_];
__device__ float g_partial[B_ * H_ * 8 * DK_];
__device__ __nv_bfloat16 g_wkhi[D_ * D_];
__device__ __nv_bfloat16 g_wklo[D_ * D_];
__device__ __nv_bfloat16 g_wghi[D_ * D_];
__device__ __nv_bfloat16 g_wglo[D_ * D_];

// ---------------- helpers ----------------------------------------------------
__device__ __forceinline__ uint32_t smem_u32(const void* p) {
    uint32_t a;
    asm("{ .reg .u64 t; cvta.to.shared.u64 t, %1; cvt.u32.u64 %0, t; }" : "=r"(a) : "l"(p));
    return a;
}
__device__ __forceinline__ uint32_t swz(uint32_t off) { return off ^ ((off >> 3) & 0x70); }

__device__ __forceinline__ void ldsm4(uint32_t* r, uint32_t addr) {
    asm volatile("ldmatrix.sync.aligned.m8n8.x4.shared.b16 {%0,%1,%2,%3}, [%4];"
        : "=r"(r[0]), "=r"(r[1]), "=r"(r[2]), "=r"(r[3]) : "r"(addr));
}
__device__ __forceinline__ void mma16816(float* d, const uint32_t* a, const uint32_t* b) {
    asm volatile("mma.sync.aligned.m16n8k16.row.col.f32.bf16.bf16.f32 "
        "{%0,%1,%2,%3}, {%4,%5,%6,%7}, {%8,%9}, {%0,%1,%2,%3};"
        : "+f"(d[0]), "+f"(d[1]), "+f"(d[2]), "+f"(d[3])
        : "r"(a[0]), "r"(a[1]), "r"(a[2]), "r"(a[3]), "r"(b[0]), "r"(b[1]));
}

// ---------------- SMEM layout (dynamic) --------------------------------------
#define SM_XHI   0          // 128x64 bf16, SW128 rows of 128B : 16 KB
#define SM_XLO   16384
#define SM_WKHI  32768      // 128 n-rows x 64 k : 16 KB each
#define SM_WKLO  49152
#define SM_WGHI  65536
#define SM_WGLO  81920
#define SM_Q     98304      // 512 f32
#define SM_SPART 100352     // 4 x 128 f32
#define SMEM_TOTAL 102400

// ---------------------------------------------------------------------------
__global__ void cvt_w_kernel(const float* __restrict__ Wk, const float* __restrict__ Wg)
{
    int i = blockIdx.x * 256 + threadIdx.x;
    float a = Wk[i];
    __nv_bfloat16 hi = __float2bfloat16(a);
    g_wkhi[i] = hi;
    g_wklo[i] = __float2bfloat16(a - __bfloat162float(hi));
    float b = Wg[i];
    __nv_bfloat16 hg = __float2bfloat16(b);
    g_wghi[i] = hg;
    g_wglo[i] = __float2bfloat16(b - __bfloat162float(hg));
}

// ---------------------------------------------------------------------------
// Pass 1: mma.sync bf16 split GEMM. 1024 CTAs x 256 thr (8 warps: 2m x 4n).
// Per CTA: 128 rows. Per head-pair: K & G accums 128x64 each, k over 512.
// ---------------------------------------------------------------------------
__global__ __launch_bounds__(256, 1)
void pass1_kernel(const float* __restrict__ x, const float* __restrict__ q)
{
    extern __shared__ char smem[];
    const uint32_t sb = smem_u32(smem);
    const int tid    = threadIdx.x;
    const int wid    = tid >> 5;
    const int lane   = tid & 31;
    const int warp_m = wid & 1;          // 64-row half
    const int warp_n = wid >> 1;         // 0..3 : (head-of-pair, col-half)

    const int row0 = blockIdx.x * 128;
    const int b    = row0 >> 13;
    const int n0   = row0 & (N_ - 1);

    for (int i = tid; i < 512; i += 256)
        ((float*)(smem + SM_Q))[i] = q[i];

    // ldmatrix lane address components (fixed per thread)
    const int a_r   = warp_m * 64 + (lane & 15);     // + mt*16
    const int a_c16 = lane >> 4;                      // + ks*2
    const int b_n   = warp_n * 32 + (lane & 7) + ((lane >> 4) << 3);  // + g*16
    const int b_c16 = (lane >> 3) & 1;                // + ks*2

    float* spart = (float*)(smem + SM_SPART);
    const float* qs = (const float*)(smem + SM_Q);

    for (int hp = 0; hp < 4; ++hp) {
        float aK[4][4][4], aG[4][4][4];
#pragma unroll
        for (int mt = 0; mt < 4; ++mt)
#pragma unroll
            for (int nt = 0; nt < 4; ++nt)
#pragma unroll
                for (int e = 0; e < 4; ++e) { aK[mt][nt][e] = 0.f; aG[mt][nt][e] = 0.f; }

        for (int c = 0; c < 8; ++c) {
            const int kk = c * 64;
            __syncthreads();

            // ---- X tile [128 x 64] f32 -> bf16 hi/lo, swizzled ----
#pragma unroll
            for (int i = 0; i < 8; ++i) {
                int idx = i * 256 + tid;            // 0..2047 float4s
                int r   = idx >> 4;
                int c4  = idx & 15;
                float4 v = *(const float4*)(x + (size_t)(row0 + r) * D_ + kk + c4 * 4);
                __nv_bfloat16 h0 = __float2bfloat16(v.x);
                __nv_bfloat16 h1 = __float2bfloat16(v.y);
                __nv_bfloat16 h2 = __float2bfloat16(v.z);
                __nv_bfloat16 h3 = __float2bfloat16(v.w);
                uint32_t hp0 = (uint32_t)__bfloat16_as_ushort(h0) | ((uint32_t)__bfloat16_as_ushort(h1) << 16);
                uint32_t hp1 = (uint32_t)__bfloat16_as_ushort(h2) | ((uint32_t)__bfloat16_as_ushort(h3) << 16);
                __nv_bfloat16 l0 = __float2bfloat16(v.x - __bfloat162float(h0));
                __nv_bfloat16 l1 = __float2bfloat16(v.y - __bfloat162float(h1));
                __nv_bfloat16 l2 = __float2bfloat16(v.z - __bfloat162float(h2));
                __nv_bfloat16 l3 = __float2bfloat16(v.w - __bfloat162float(h3));
                uint32_t lp0 = (uint32_t)__bfloat16_as_ushort(l0) | ((uint32_t)__bfloat16_as_ushort(l1) << 16);
                uint32_t lp1 = (uint32_t)__bfloat16_as_ushort(l2) | ((uint32_t)__bfloat16_as_ushort(l3) << 16);
                uint32_t sw = swz((uint32_t)(r * 128 + c4 * 8));
                *(uint2*)(smem + SM_XHI + sw) = make_uint2(hp0, hp1);
                *(uint2*)(smem + SM_XLO + sw) = make_uint2(lp0, lp1);
            }

            // ---- W tiles: 4 arrays x [128 n-rows x 64 k] bf16, swizzled ----
            {
                const __nv_bfloat16* wsrc[4] = { g_wkhi, g_wklo, g_wghi, g_wglo };
                const uint32_t wdst[4] = { SM_WKHI, SM_WKLO, SM_WGHI, SM_WGLO };
#pragma unroll
                for (int a = 0; a < 4; ++a) {
#pragma unroll
                    for (int i = 0; i < 4; ++i) {
                        int idx = i * 256 + tid;    // 0..1023 uint4s
                        int r   = idx >> 3;
                        int cc  = idx & 7;
                        uint4 v = *(const uint4*)(wsrc[a] + (size_t)(hp * 128 + r) * D_ + kk + cc * 8);
                        *(uint4*)(smem + wdst[a] + swz((uint32_t)(r * 128 + cc * 16))) = v;
                    }
                }
            }
            __syncthreads();

            // ---- MMAs: 4 k-steps of 16 ----
#pragma unroll
            for (int ks = 0; ks < 4; ++ks) {
                uint32_t Ahi[4][4], Alo[4][4];
#pragma unroll
                for (int mt = 0; mt < 4; ++mt) {
                    uint32_t off = swz((uint32_t)((a_r + mt * 16) * 128 + (a_c16 + ks * 2) * 16));
                    ldsm4(Ahi[mt], sb + SM_XHI + off);
                    ldsm4(Alo[mt], sb + SM_XLO + off);
                }
                // K then G
#pragma unroll
                for (int s = 0; s < 2; ++s) {
                    const uint32_t bhi = s ? SM_WGHI : SM_WKHI;
                    const uint32_t blo = s ? SM_WGLO : SM_WKLO;
                    uint32_t Bh[2][4], Bl[2][4];
#pragma unroll
                    for (int g = 0; g < 2; ++g) {
                        uint32_t off = swz((uint32_t)((b_n + g * 16) * 128 + (b_c16 + ks * 2) * 16));
                        ldsm4(Bh[g], sb + bhi + off);
                        ldsm4(Bl[g], sb + blo + off);
                    }
#pragma unroll
                    for (int mt = 0; mt < 4; ++mt) {
#pragma unroll
                        for (int nt = 0; nt < 4; ++nt) {
                            float* acc = s ? aG[mt][nt] : aK[mt][nt];
                            const uint32_t* bh = &Bh[nt >> 1][(nt & 1) * 2];
                            const uint32_t* bl = &Bl[nt >> 1][(nt & 1) * 2];
                            mma16816(acc, Ahi[mt], bh);
                            mma16816(acc, Ahi[mt], bl);
                            mma16816(acc, Alo[mt], bh);
                        }
                    }
                }
            }
        }

        // ---- epilogue: gate + q-dot ----
        const int head = hp * 2 + (warp_n >> 1);
        const int cb   = (warp_n & 1) * 32 + 2 * (lane & 3);
#pragma unroll
        for (int mt = 0; mt < 4; ++mt) {
            float p0 = 0.f, p1 = 0.f;
#pragma unroll
            for (int nt = 0; nt < 4; ++nt) {
                int col = cb + nt * 8;
                float q0 = qs[head * 64 + col];
                float q1 = qs[head * 64 + col + 1];
                const float* K = aK[mt][nt];
                const float* G = aG[mt][nt];
                p0 += q0 * tanhf(K[0]) * (1.f / (1.f + __expf(-G[0])));
                p0 += q1 * tanhf(K[1]) * (1.f / (1.f + __expf(-G[1])));
                p1 += q0 * tanhf(K[2]) * (1.f / (1.f + __expf(-G[2])));
                p1 += q1 * tanhf(K[3]) * (1.f / (1.f + __expf(-G[3])));
            }
            p0 += __shfl_xor_sync(0xffffffffu, p0, 1);
            p0 += __shfl_xor_sync(0xffffffffu, p0, 2);
            p1 += __shfl_xor_sync(0xffffffffu, p1, 1);
            p1 += __shfl_xor_sync(0xffffffffu, p1, 2);
            if ((lane & 3) == 0) {
                int row = warp_m * 64 + mt * 16 + (lane >> 2);
                spart[warp_n * 128 + row]     = p0;
                spart[warp_n * 128 + row + 8] = p1;
            }
        }
        __syncthreads();
        {
            int row = tid & 127;
            int hh  = tid >> 7;         // 0..1
            float s = spart[(2 * hh) * 128 + row] + spart[(2 * hh + 1) * 128 + row];
            g_scores[((size_t)b * H_ + hp * 2 + hh) * N_ + n0 + row] = s;
        }
    }
}

// ---------------------------------------------------------------------------
__global__ __launch_bounds__(512)
void pass2a_kernel()
{
    __shared__ float red[16];
    const int bh  = blockIdx.x;
    const int tid = threadIdx.x;
    float* sc = g_scores + (size_t)bh * N_;

    float mx = -1e30f;
    for (int i = tid; i < N_; i += 512) mx = fmaxf(mx, sc[i]);
#pragma unroll
    for (int off = 16; off >= 1; off >>= 1)
        mx = fmaxf(mx, __shfl_xor_sync(0xffffffffu, mx, off));
    if ((tid & 31) == 0) red[tid >> 5] = mx;
    __syncthreads();
    if (tid < 32) {
        float v = (tid < 16) ? red[tid] : -1e30f;
#pragma unroll
        for (int off = 8; off >= 1; off >>= 1)
            v = fmaxf(v, __shfl_xor_sync(0xffffffffu, v, off));
        if (tid == 0) red[0] = v;
    }
    __syncthreads();
    mx = red[0];
    __syncthreads();

    float sum = 0.f;
    for (int i = tid; i < N_; i += 512) {
        float e = __expf(sc[i] - mx);
        sc[i] = e;
        sum += e;
    }
#pragma unroll
    for (int off = 16; off >= 1; off >>= 1)
        sum += __shfl_xor_sync(0xffffffffu, sum, off);
    if ((tid & 31) == 0) red[tid >> 5] = sum;
    __syncthreads();
    if (tid < 32) {
        float v = (tid < 16) ? red[tid] : 0.f;
#pragma unroll
        for (int off = 8; off >= 1; off >>= 1)
            v += __shfl_xor_sync(0xffffffffu, v, off);
        if (tid == 0) g_inv[bh] = 1.f / v;
    }
}

__global__ __launch_bounds__(256)
void pass2b_kernel(const float* __restrict__ x)
{
    __shared__ float red[256];
    const int bh = blockIdx.x >> 3;
    const int ch = blockIdx.x & 7;
    const int b  = bh >> 3;
    const int h  = bh & 7;
    const int tid = threadIdx.x;
    const int d   = tid & 63;
    const int sl  = tid >> 6;

    const float* w  = g_scores + (size_t)bh * N_;
    const float* xp = x + (size_t)b * N_ * D_ + h * DK_ + d;
    const int base = ch * 1024;

    float a = 0.f;
    for (int n = base + sl; n < base + 1024; n += 16) {
        a = fmaf(w[n],      xp[(size_t)(n)      * D_], a);
        a = fmaf(w[n + 4],  xp[(size_t)(n + 4)  * D_], a);
        a = fmaf(w[n + 8],  xp[(size_t)(n + 8)  * D_], a);
        a = fmaf(w[n + 12], xp[(size_t)(n + 12) * D_], a);
    }
    red[tid] = a;
    __syncthreads();
    if (tid < 64)
        g_partial[((size_t)bh * 8 + ch) * DK_ + tid] =
            (red[tid] + red[tid + 64]) + (red[tid + 128] + red[tid + 192]);
}

__global__ __launch_bounds__(512)
void pass2c_kernel(float* __restrict__ out)
{
    const int b   = blockIdx.x;
    const int col = threadIdx.x;
    const int h   = col >> 6;
    const int d   = col & 63;
    const int bh  = b * 8 + h;
    float s = 0.f;
#pragma unroll
    for (int ch = 0; ch < 8; ++ch)
        s += g_partial[((size_t)bh * 8 + ch) * DK_ + d];
    out[(size_t)b * D_ + col] = s * g_inv[bh];
}

// ---------------------------------------------------------------------------
extern "C" void kernel_launch(void* const* d_in, const int* in_sizes, int n_in,
                              void* d_out, int out_size)
{
    const float* x  = (const float*)d_in[0];
    const float* Wk = (const float*)d_in[1];
    const float* Wg = (const float*)d_in[2];
    const float* q  = (const float*)d_in[3];
    float* out = (float*)d_out;

    cudaFuncSetAttribute(pass1_kernel, cudaFuncAttributeMaxDynamicSharedMemorySize, SMEM_TOTAL);

    cvt_w_kernel<<<1024, 256>>>(Wk, Wg);
    pass1_kernel<<<ROWS_ / 128, 256, SMEM_TOTAL>>>(x, q);
    pass2a_kernel<<<B_ * H_, 512>>>();
    pass2b_kernel<<<B_ * H_ * 8, 256>>>(x);
    pass2c_kernel<<<B_, 512>>>(out);
}

// round 4
// speedup vs baseline: 4.3385x; 1.1452x over previous
#include <cuda_runtime.h>
#include <cuda_bf16.h>
#include <cstdint>

#define H_  8
#define D_  512
#define DK_ 64
#define B_  16
#define N_  8192
#define ROWS_ (B_ * N_)

// ---------------- device scratch ---------------------------------------------
__device__ float g_scores[B_ * H_ * N_];                 // scores -> exp weights
__device__ float g_inv[B_ * H_];
__device__ float g_partial[B_ * H_ * 8 * DK_];
__device__ __nv_bfloat16 g_wkhi[D_ * D_];
__device__ __nv_bfloat16 g_wklo[D_ * D_];
__device__ __nv_bfloat16 g_wghi[D_ * D_];
__device__ __nv_bfloat16 g_wglo[D_ * D_];
__device__ __nv_bfloat16 g_xhi[(size_t)ROWS_ * D_];      // 128 MB
__device__ __nv_bfloat16 g_xlo[(size_t)ROWS_ * D_];      // 128 MB

// ---------------- helpers ----------------------------------------------------
__device__ __forceinline__ uint32_t smem_u32(const void* p) {
    uint32_t a;
    asm("{ .reg .u64 t; cvta.to.shared.u64 t, %1; cvt.u32.u64 %0, t; }" : "=r"(a) : "l"(p));
    return a;
}
__device__ __forceinline__ uint32_t swz(uint32_t off) { return off ^ ((off >> 3) & 0x70); }

__device__ __forceinline__ void ldsm4(uint32_t* r, uint32_t addr) {
    asm volatile("ldmatrix.sync.aligned.m8n8.x4.shared.b16 {%0,%1,%2,%3}, [%4];"
        : "=r"(r[0]), "=r"(r[1]), "=r"(r[2]), "=r"(r[3]) : "r"(addr));
}
__device__ __forceinline__ void mma16816(float* d, const uint32_t* a, const uint32_t* b) {
    asm volatile("mma.sync.aligned.m16n8k16.row.col.f32.bf16.bf16.f32 "
        "{%0,%1,%2,%3}, {%4,%5,%6,%7}, {%8,%9}, {%0,%1,%2,%3};"
        : "+f"(d[0]), "+f"(d[1]), "+f"(d[2]), "+f"(d[3])
        : "r"(a[0]), "r"(a[1]), "r"(a[2]), "r"(a[3]), "r"(b[0]), "r"(b[1]));
}
#define CP16(dst, src) asm volatile("cp.async.cg.shared.global [%0], [%1], 16;" :: "r"(dst), "l"(src) : "memory")
#define CP_COMMIT()    asm volatile("cp.async.commit_group;" ::: "memory")
#define CP_WAIT1()     asm volatile("cp.async.wait_group 1;" ::: "memory")
#define CP_WAIT0()     asm volatile("cp.async.wait_group 0;" ::: "memory")

// ---------------- SMEM layout: two 96KB stages + q + spart -------------------
#define SM_STAGE  98304
#define SMX_HI    0
#define SMX_LO    16384
#define SMW       32768      // +a*16384, a = {wkhi, wklo, wghi, wglo}
#define SM_Q      (2 * SM_STAGE)          // 196608
#define SM_SPART  (SM_Q + 2048)           // 198656
#define SMEM_TOTAL (SM_SPART + 2048)      // 200704

// ---------------------------------------------------------------------------
__global__ void cvt_w_kernel(const float* __restrict__ Wk, const float* __restrict__ Wg)
{
    int i = blockIdx.x * 256 + threadIdx.x;
    float a = Wk[i];
    __nv_bfloat16 hi = __float2bfloat16(a);
    g_wkhi[i] = hi;
    g_wklo[i] = __float2bfloat16(a - __bfloat162float(hi));
    float b = Wg[i];
    __nv_bfloat16 hg = __float2bfloat16(b);
    g_wghi[i] = hg;
    g_wglo[i] = __float2bfloat16(b - __bfloat162float(hg));
}

__global__ __launch_bounds__(256)
void cvt_x_kernel(const float* __restrict__ x)
{
    size_t i = ((size_t)blockIdx.x * 256 + threadIdx.x) * 4;
    float4 v = *(const float4*)(x + i);
    __nv_bfloat16 h0 = __float2bfloat16(v.x);
    __nv_bfloat16 h1 = __float2bfloat16(v.y);
    __nv_bfloat16 h2 = __float2bfloat16(v.z);
    __nv_bfloat16 h3 = __float2bfloat16(v.w);
    uint32_t hp0 = (uint32_t)__bfloat16_as_ushort(h0) | ((uint32_t)__bfloat16_as_ushort(h1) << 16);
    uint32_t hp1 = (uint32_t)__bfloat16_as_ushort(h2) | ((uint32_t)__bfloat16_as_ushort(h3) << 16);
    __nv_bfloat16 l0 = __float2bfloat16(v.x - __bfloat162float(h0));
    __nv_bfloat16 l1 = __float2bfloat16(v.y - __bfloat162float(h1));
    __nv_bfloat16 l2 = __float2bfloat16(v.z - __bfloat162float(h2));
    __nv_bfloat16 l3 = __float2bfloat16(v.w - __bfloat162float(h3));
    uint32_t lp0 = (uint32_t)__bfloat16_as_ushort(l0) | ((uint32_t)__bfloat16_as_ushort(l1) << 16);
    uint32_t lp1 = (uint32_t)__bfloat16_as_ushort(l2) | ((uint32_t)__bfloat16_as_ushort(l3) << 16);
    *(uint2*)(g_xhi + i) = make_uint2(hp0, hp1);
    *(uint2*)(g_xlo + i) = make_uint2(lp0, lp1);
}

// ---------------------------------------------------------------------------
// Stage loader: X hi/lo tile [128x64] + 4 W tiles [128x64] via cp.async 16B.
// ---------------------------------------------------------------------------
__device__ __forceinline__ void load_stage(uint32_t sb, int s, int it, int row0)
{
    const int tid = threadIdx.x;
    const int hp  = it >> 3;
    const int kk  = (it & 7) << 6;
    const uint32_t st = sb + (uint32_t)s * SM_STAGE;

#pragma unroll
    for (int i = 0; i < 4; ++i) {
        int idx = i * 256 + tid;            // 0..1023 16B chunks
        int r   = idx >> 3;
        int cc  = idx & 7;
        uint32_t dsw = swz((uint32_t)(r * 128 + cc * 16));
        CP16(st + SMX_HI + dsw, g_xhi + (size_t)(row0 + r) * D_ + kk + cc * 8);
        CP16(st + SMX_LO + dsw, g_xlo + (size_t)(row0 + r) * D_ + kk + cc * 8);
    }
    const __nv_bfloat16* wsrc[4] = { g_wkhi, g_wklo, g_wghi, g_wglo };
#pragma unroll
    for (int a = 0; a < 4; ++a) {
        const __nv_bfloat16* src = wsrc[a] + (size_t)(hp * 128) * D_ + kk;
        const uint32_t dst = st + SMW + (uint32_t)a * 16384;
#pragma unroll
        for (int i = 0; i < 4; ++i) {
            int idx = i * 256 + tid;
            int r   = idx >> 3;
            int cc  = idx & 7;
            CP16(dst + swz((uint32_t)(r * 128 + cc * 16)), src + (size_t)r * D_ + cc * 8);
        }
    }
}

// ---------------------------------------------------------------------------
// Pass 1: cp.async double-buffered mma.sync bf16-split GEMM + gate + q-dot.
// 1024 CTAs x 256 thr (8 warps: 2m x 4n). 32 pipelined iterations.
// ---------------------------------------------------------------------------
__global__ __launch_bounds__(256, 1)
void pass1_kernel(const float* __restrict__ q)
{
    extern __shared__ char smem[];
    const uint32_t sb = smem_u32(smem);
    const int tid    = threadIdx.x;
    const int lane   = tid & 31;
    const int wid    = tid >> 5;
    const int warp_m = wid & 1;
    const int warp_n = wid >> 1;

    const int row0 = blockIdx.x * 128;
    const int b    = row0 >> 13;
    const int n0   = row0 & (N_ - 1);

    for (int i = tid; i < 512; i += 256)
        ((float*)(smem + SM_Q))[i] = q[i];

    const int a_r   = warp_m * 64 + (lane & 15);
    const int a_c16 = lane >> 4;
    const int b_n   = warp_n * 32 + (lane & 7) + ((lane >> 4) << 3);
    const int b_c16 = (lane >> 3) & 1;

    float* spart = (float*)(smem + SM_SPART);
    const float* qs = (const float*)(smem + SM_Q);

    float aK[4][4][4], aG[4][4][4];

    load_stage(sb, 0, 0, row0);
    CP_COMMIT();

    for (int it = 0; it < 32; ++it) {
        const int s  = it & 1;
        const int c  = it & 7;
        const int hp = it >> 3;
        const uint32_t st = sb + (uint32_t)s * SM_STAGE;

        if (c == 0) {
#pragma unroll
            for (int mt = 0; mt < 4; ++mt)
#pragma unroll
                for (int nt = 0; nt < 4; ++nt)
#pragma unroll
                    for (int e = 0; e < 4; ++e) { aK[mt][nt][e] = 0.f; aG[mt][nt][e] = 0.f; }
        }

        if (it < 31) {
            load_stage(sb, s ^ 1, it + 1, row0);
            CP_COMMIT();
            CP_WAIT1();
        } else {
            CP_WAIT0();
        }
        __syncthreads();

        // ---- MMAs: 4 k-steps of 16 ----
#pragma unroll
        for (int ks = 0; ks < 4; ++ks) {
            uint32_t Ahi[4][4], Alo[4][4];
#pragma unroll
            for (int mt = 0; mt < 4; ++mt) {
                uint32_t off = swz((uint32_t)((a_r + mt * 16) * 128 + (a_c16 + ks * 2) * 16));
                ldsm4(Ahi[mt], st + SMX_HI + off);
                ldsm4(Alo[mt], st + SMX_LO + off);
            }
#pragma unroll
            for (int sel = 0; sel < 2; ++sel) {
                const uint32_t bhi = st + SMW + (uint32_t)(sel * 2)     * 16384;
                const uint32_t blo = st + SMW + (uint32_t)(sel * 2 + 1) * 16384;
                uint32_t Bh[2][4], Bl[2][4];
#pragma unroll
                for (int g = 0; g < 2; ++g) {
                    uint32_t off = swz((uint32_t)((b_n + g * 16) * 128 + (b_c16 + ks * 2) * 16));
                    ldsm4(Bh[g], bhi + off);
                    ldsm4(Bl[g], blo + off);
                }
#pragma unroll
                for (int mt = 0; mt < 4; ++mt) {
#pragma unroll
                    for (int nt = 0; nt < 4; ++nt) {
                        float* acc = sel ? aG[mt][nt] : aK[mt][nt];
                        const uint32_t* bh = &Bh[nt >> 1][(nt & 1) * 2];
                        const uint32_t* bl = &Bl[nt >> 1][(nt & 1) * 2];
                        mma16816(acc, Ahi[mt], bh);
                        mma16816(acc, Ahi[mt], bl);
                        mma16816(acc, Alo[mt], bh);
                    }
                }
            }
        }

        if (c < 7) {
            __syncthreads();
        } else {
            // ---- epilogue: gate + q-dot -> scores for this head-pair ----
            const int head = hp * 2 + (warp_n >> 1);
            const int cb   = (warp_n & 1) * 32 + 2 * (lane & 3);
#pragma unroll
            for (int mt = 0; mt < 4; ++mt) {
                float p0 = 0.f, p1 = 0.f;
#pragma unroll
                for (int nt = 0; nt < 4; ++nt) {
                    int col = cb + nt * 8;
                    float q0 = qs[head * 64 + col];
                    float q1 = qs[head * 64 + col + 1];
                    const float* K = aK[mt][nt];
                    const float* G = aG[mt][nt];
                    p0 += q0 * tanhf(K[0]) * (1.f / (1.f + __expf(-G[0])));
                    p0 += q1 * tanhf(K[1]) * (1.f / (1.f + __expf(-G[1])));
                    p1 += q0 * tanhf(K[2]) * (1.f / (1.f + __expf(-G[2])));
                    p1 += q1 * tanhf(K[3]) * (1.f / (1.f + __expf(-G[3])));
                }
                p0 += __shfl_xor_sync(0xffffffffu, p0, 1);
                p0 += __shfl_xor_sync(0xffffffffu, p0, 2);
                p1 += __shfl_xor_sync(0xffffffffu, p1, 1);
                p1 += __shfl_xor_sync(0xffffffffu, p1, 2);
                if ((lane & 3) == 0) {
                    int row = warp_m * 64 + mt * 16 + (lane >> 2);
                    spart[warp_n * 128 + row]     = p0;
                    spart[warp_n * 128 + row + 8] = p1;
                }
            }
            __syncthreads();
            {
                int row = tid & 127;
                int hh  = tid >> 7;
                float sc = spart[(2 * hh) * 128 + row] + spart[(2 * hh + 1) * 128 + row];
                g_scores[((size_t)b * H_ + hp * 2 + hh) * N_ + n0 + row] = sc;
            }
            __syncthreads();
        }
    }
}

// ---------------------------------------------------------------------------
__global__ __launch_bounds__(512)
void pass2a_kernel()
{
    __shared__ float red[16];
    const int bh  = blockIdx.x;
    const int tid = threadIdx.x;
    float* sc = g_scores + (size_t)bh * N_;

    float mx = -1e30f;
    for (int i = tid; i < N_; i += 512) mx = fmaxf(mx, sc[i]);
#pragma unroll
    for (int off = 16; off >= 1; off >>= 1)
        mx = fmaxf(mx, __shfl_xor_sync(0xffffffffu, mx, off));
    if ((tid & 31) == 0) red[tid >> 5] = mx;
    __syncthreads();
    if (tid < 32) {
        float v = (tid < 16) ? red[tid] : -1e30f;
#pragma unroll
        for (int off = 8; off >= 1; off >>= 1)
            v = fmaxf(v, __shfl_xor_sync(0xffffffffu, v, off));
        if (tid == 0) red[0] = v;
    }
    __syncthreads();
    mx = red[0];
    __syncthreads();

    float sum = 0.f;
    for (int i = tid; i < N_; i += 512) {
        float e = __expf(sc[i] - mx);
        sc[i] = e;
        sum += e;
    }
#pragma unroll
    for (int off = 16; off >= 1; off >>= 1)
        sum += __shfl_xor_sync(0xffffffffu, sum, off);
    if ((tid & 31) == 0) red[tid >> 5] = sum;
    __syncthreads();
    if (tid < 32) {
        float v = (tid < 16) ? red[tid] : 0.f;
#pragma unroll
        for (int off = 8; off >= 1; off >>= 1)
            v += __shfl_xor_sync(0xffffffffu, v, off);
        if (tid == 0) g_inv[bh] = 1.f / v;
    }
}

__global__ __launch_bounds__(256)
void pass2b_kernel(const float* __restrict__ x)
{
    __shared__ float red[256];
    const int bh = blockIdx.x >> 3;
    const int ch = blockIdx.x & 7;
    const int b  = bh >> 3;
    const int h  = bh & 7;
    const int tid = threadIdx.x;
    const int d   = tid & 63;
    const int sl  = tid >> 6;

    const float* w  = g_scores + (size_t)bh * N_;
    const float* xp = x + (size_t)b * N_ * D_ + h * DK_ + d;
    const int base = ch * 1024;

    float a = 0.f;
    for (int n = base + sl; n < base + 1024; n += 16) {
        a = fmaf(w[n],      xp[(size_t)(n)      * D_], a);
        a = fmaf(w[n + 4],  xp[(size_t)(n + 4)  * D_], a);
        a = fmaf(w[n + 8],  xp[(size_t)(n + 8)  * D_], a);
        a = fmaf(w[n + 12], xp[(size_t)(n + 12) * D_], a);
    }
    red[tid] = a;
    __syncthreads();
    if (tid < 64)
        g_partial[((size_t)bh * 8 + ch) * DK_ + tid] =
            (red[tid] + red[tid + 64]) + (red[tid + 128] + red[tid + 192]);
}

__global__ __launch_bounds__(512)
void pass2c_kernel(float* __restrict__ out)
{
    const int b   = blockIdx.x;
    const int col = threadIdx.x;
    const int h   = col >> 6;
    const int d   = col & 63;
    const int bh  = b * 8 + h;
    float s = 0.f;
#pragma unroll
    for (int ch = 0; ch < 8; ++ch)
        s += g_partial[((size_t)bh * 8 + ch) * DK_ + d];
    out[(size_t)b * D_ + col] = s * g_inv[bh];
}

// ---------------------------------------------------------------------------
extern "C" void kernel_launch(void* const* d_in, const int* in_sizes, int n_in,
                              void* d_out, int out_size)
{
    const float* x  = (const float*)d_in[0];
    const float* Wk = (const float*)d_in[1];
    const float* Wg = (const float*)d_in[2];
    const float* q  = (const float*)d_in[3];
    float* out = (float*)d_out;

    cudaFuncSetAttribute(pass1_kernel, cudaFuncAttributeMaxDynamicSharedMemorySize, SMEM_TOTAL);

    cvt_w_kernel<<<1024, 256>>>(Wk, Wg);
    cvt_x_kernel<<<(int)((size_t)ROWS_ * D_ / 1024), 256>>>(x);
    pass1_kernel<<<ROWS_ / 128, 256, SMEM_TOTAL>>>(q);
    pass2a_kernel<<<B_ * H_, 512>>>();
    pass2b_kernel<<<B_ * H_ * 8, 256>>>(x);
    pass2c_kernel<<<B_, 512>>>(out);
}

// round 5
// speedup vs baseline: 4.7540x; 1.0958x over previous
#include <cuda_runtime.h>
#include <cuda_bf16.h>
#include <cstdint>

#define H_  8
#define D_  512
#define DK_ 64
#define B_  16
#define N_  8192
#define ROWS_ (B_ * N_)

// ---------------- device scratch ---------------------------------------------
__device__ float g_scores[B_ * H_ * N_];                 // scores -> exp weights
__device__ float g_inv[B_ * H_];
__device__ float g_partial[B_ * H_ * 16 * DK_];
__device__ __nv_bfloat16 g_wkhi[D_ * D_];
__device__ __nv_bfloat16 g_wklo[D_ * D_];
__device__ __nv_bfloat16 g_wghi[D_ * D_];
__device__ __nv_bfloat16 g_wglo[D_ * D_];
__device__ __nv_bfloat16 g_xhi[(size_t)ROWS_ * D_];      // 128 MB
__device__ __nv_bfloat16 g_xlo[(size_t)ROWS_ * D_];      // 128 MB

// ---------------- helpers ----------------------------------------------------
__device__ __forceinline__ uint32_t smem_u32(const void* p) {
    uint32_t a;
    asm("{ .reg .u64 t; cvta.to.shared.u64 t, %1; cvt.u32.u64 %0, t; }" : "=r"(a) : "l"(p));
    return a;
}
__device__ __forceinline__ uint32_t swz(uint32_t off) { return off ^ ((off >> 3) & 0x70); }

__device__ __forceinline__ void ldsm4(uint32_t* r, uint32_t addr) {
    asm volatile("ldmatrix.sync.aligned.m8n8.x4.shared.b16 {%0,%1,%2,%3}, [%4];"
        : "=r"(r[0]), "=r"(r[1]), "=r"(r[2]), "=r"(r[3]) : "r"(addr));
}
__device__ __forceinline__ void mma16816(float* d, const uint32_t* a, const uint32_t* b) {
    asm volatile("mma.sync.aligned.m16n8k16.row.col.f32.bf16.bf16.f32 "
        "{%0,%1,%2,%3}, {%4,%5,%6,%7}, {%8,%9}, {%0,%1,%2,%3};"
        : "+f"(d[0]), "+f"(d[1]), "+f"(d[2]), "+f"(d[3])
        : "r"(a[0]), "r"(a[1]), "r"(a[2]), "r"(a[3]), "r"(b[0]), "r"(b[1]));
}
#define CP16(dst, src) asm volatile("cp.async.cg.shared.global [%0], [%1], 16;" :: "r"(dst), "l"(src) : "memory")
#define CP_COMMIT()    asm volatile("cp.async.commit_group;" ::: "memory")
#define CP_WAIT1()     asm volatile("cp.async.wait_group 1;" ::: "memory")
#define CP_WAIT0()     asm volatile("cp.async.wait_group 0;" ::: "memory")

// fused gate: tanh(k) * sigmoid(g) = (e^{2k}-1) / ((e^{2k}+1)(1+e^{-g}))
__device__ __forceinline__ float gatefn(float k, float g) {
    float t  = __expf(2.f * k);
    float eg = __expf(-g);
    return __fdividef(t - 1.f, (t + 1.f) * (1.f + eg));
}

// ---------------- SMEM layout: two 96KB stages + q + spart -------------------
#define SM_STAGE  98304
#define SMX_HI    0
#define SMX_LO    16384
#define SMW       32768      // +a*16384, a = {wkhi, wklo, wghi, wglo}
#define SM_Q      (2 * SM_STAGE)          // 196608
#define SM_SPART  (SM_Q + 2048)           // 198656
#define SMEM_TOTAL (SM_SPART + 2048)      // 200704

// ---------------------------------------------------------------------------
__global__ void cvt_w_kernel(const float* __restrict__ Wk, const float* __restrict__ Wg)
{
    int i = blockIdx.x * 256 + threadIdx.x;
    float a = Wk[i];
    __nv_bfloat16 hi = __float2bfloat16(a);
    g_wkhi[i] = hi;
    g_wklo[i] = __float2bfloat16(a - __bfloat162float(hi));
    float b = Wg[i];
    __nv_bfloat16 hg = __float2bfloat16(b);
    g_wghi[i] = hg;
    g_wglo[i] = __float2bfloat16(b - __bfloat162float(hg));
}

__global__ __launch_bounds__(256)
void cvt_x_kernel(const float* __restrict__ x)
{
    size_t i = ((size_t)blockIdx.x * 256 + threadIdx.x) * 4;
    float4 v = *(const float4*)(x + i);
    __nv_bfloat16 h0 = __float2bfloat16(v.x);
    __nv_bfloat16 h1 = __float2bfloat16(v.y);
    __nv_bfloat16 h2 = __float2bfloat16(v.z);
    __nv_bfloat16 h3 = __float2bfloat16(v.w);
    uint32_t hp0 = (uint32_t)__bfloat16_as_ushort(h0) | ((uint32_t)__bfloat16_as_ushort(h1) << 16);
    uint32_t hp1 = (uint32_t)__bfloat16_as_ushort(h2) | ((uint32_t)__bfloat16_as_ushort(h3) << 16);
    __nv_bfloat16 l0 = __float2bfloat16(v.x - __bfloat162float(h0));
    __nv_bfloat16 l1 = __float2bfloat16(v.y - __bfloat162float(h1));
    __nv_bfloat16 l2 = __float2bfloat16(v.z - __bfloat162float(h2));
    __nv_bfloat16 l3 = __float2bfloat16(v.w - __bfloat162float(h3));
    uint32_t lp0 = (uint32_t)__bfloat16_as_ushort(l0) | ((uint32_t)__bfloat16_as_ushort(l1) << 16);
    uint32_t lp1 = (uint32_t)__bfloat16_as_ushort(l2) | ((uint32_t)__bfloat16_as_ushort(l3) << 16);
    *(uint2*)(g_xhi + i) = make_uint2(hp0, hp1);
    *(uint2*)(g_xlo + i) = make_uint2(lp0, lp1);
}

// ---------------------------------------------------------------------------
// Stage loader: X hi/lo tile [128x64] + 4 W tiles [128x64] via cp.async 16B.
// ---------------------------------------------------------------------------
__device__ __forceinline__ void load_stage(uint32_t sb, int s, int it, int row0)
{
    const int tid = threadIdx.x;
    const int hp  = it >> 3;
    const int kk  = (it & 7) << 6;
    const uint32_t st = sb + (uint32_t)s * SM_STAGE;

#pragma unroll
    for (int i = 0; i < 4; ++i) {
        int idx = i * 256 + tid;            // 0..1023 16B chunks
        int r   = idx >> 3;
        int cc  = idx & 7;
        uint32_t dsw = swz((uint32_t)(r * 128 + cc * 16));
        CP16(st + SMX_HI + dsw, g_xhi + (size_t)(row0 + r) * D_ + kk + cc * 8);
        CP16(st + SMX_LO + dsw, g_xlo + (size_t)(row0 + r) * D_ + kk + cc * 8);
    }
    const __nv_bfloat16* wsrc[4] = { g_wkhi, g_wklo, g_wghi, g_wglo };
#pragma unroll
    for (int a = 0; a < 4; ++a) {
        const __nv_bfloat16* src = wsrc[a] + (size_t)(hp * 128) * D_ + kk;
        const uint32_t dst = st + SMW + (uint32_t)a * 16384;
#pragma unroll
        for (int i = 0; i < 4; ++i) {
            int idx = i * 256 + tid;
            int r   = idx >> 3;
            int cc  = idx & 7;
            CP16(dst + swz((uint32_t)(r * 128 + cc * 16)), src + (size_t)r * D_ + cc * 8);
        }
    }
}

// ---------------------------------------------------------------------------
// Pass 1: cp.async double-buffered mma.sync bf16-split GEMM + gate + q-dot.
// 1024 CTAs x 256 thr (8 warps: 2m x 4n). 32 pipelined iterations.
// ---------------------------------------------------------------------------
__global__ __launch_bounds__(256, 1)
void pass1_kernel(const float* __restrict__ q)
{
    extern __shared__ char smem[];
    const uint32_t sb = smem_u32(smem);
    const int tid    = threadIdx.x;
    const int lane   = tid & 31;
    const int wid    = tid >> 5;
    const int warp_m = wid & 1;
    const int warp_n = wid >> 1;

    const int row0 = blockIdx.x * 128;
    const int b    = row0 >> 13;
    const int n0   = row0 & (N_ - 1);

    for (int i = tid; i < 512; i += 256)
        ((float*)(smem + SM_Q))[i] = q[i];

    const int a_r   = warp_m * 64 + (lane & 15);
    const int a_c16 = lane >> 4;
    const int b_n   = warp_n * 32 + (lane & 7) + ((lane >> 4) << 3);
    const int b_c16 = (lane >> 3) & 1;

    float* spart = (float*)(smem + SM_SPART);
    const float* qs = (const float*)(smem + SM_Q);

    float aK[4][4][4], aG[4][4][4];

    load_stage(sb, 0, 0, row0);
    CP_COMMIT();

    for (int it = 0; it < 32; ++it) {
        const int s  = it & 1;
        const int c  = it & 7;
        const int hp = it >> 3;
        const uint32_t st = sb + (uint32_t)s * SM_STAGE;

        if (c == 0) {
#pragma unroll
            for (int mt = 0; mt < 4; ++mt)
#pragma unroll
                for (int nt = 0; nt < 4; ++nt)
#pragma unroll
                    for (int e = 0; e < 4; ++e) { aK[mt][nt][e] = 0.f; aG[mt][nt][e] = 0.f; }
        }

        if (it < 31) {
            load_stage(sb, s ^ 1, it + 1, row0);
            CP_COMMIT();
            CP_WAIT1();
        } else {
            CP_WAIT0();
        }
        __syncthreads();

        // ---- MMAs: 4 k-steps of 16 ----
#pragma unroll
        for (int ks = 0; ks < 4; ++ks) {
            uint32_t Ahi[4][4], Alo[4][4];
#pragma unroll
            for (int mt = 0; mt < 4; ++mt) {
                uint32_t off = swz((uint32_t)((a_r + mt * 16) * 128 + (a_c16 + ks * 2) * 16));
                ldsm4(Ahi[mt], st + SMX_HI + off);
                ldsm4(Alo[mt], st + SMX_LO + off);
            }
#pragma unroll
            for (int sel = 0; sel < 2; ++sel) {
                const uint32_t bhi = st + SMW + (uint32_t)(sel * 2)     * 16384;
                const uint32_t blo = st + SMW + (uint32_t)(sel * 2 + 1) * 16384;
                uint32_t Bh[2][4], Bl[2][4];
#pragma unroll
                for (int g = 0; g < 2; ++g) {
                    uint32_t off = swz((uint32_t)((b_n + g * 16) * 128 + (b_c16 + ks * 2) * 16));
                    ldsm4(Bh[g], bhi + off);
                    ldsm4(Bl[g], blo + off);
                }
#pragma unroll
                for (int mt = 0; mt < 4; ++mt) {
#pragma unroll
                    for (int nt = 0; nt < 4; ++nt) {
                        float* acc = sel ? aG[mt][nt] : aK[mt][nt];
                        const uint32_t* bh = &Bh[nt >> 1][(nt & 1) * 2];
                        const uint32_t* bl = &Bl[nt >> 1][(nt & 1) * 2];
                        mma16816(acc, Ahi[mt], bh);
                        mma16816(acc, Ahi[mt], bl);
                        mma16816(acc, Alo[mt], bh);
                    }
                }
            }
        }

        if (c < 7) {
            __syncthreads();
        } else {
            // ---- epilogue: fused gate + q-dot -> scores for this head-pair ----
            const int head = hp * 2 + (warp_n >> 1);
            const int cb   = (warp_n & 1) * 32 + 2 * (lane & 3);
#pragma unroll
            for (int mt = 0; mt < 4; ++mt) {
                float p0 = 0.f, p1 = 0.f;
#pragma unroll
                for (int nt = 0; nt < 4; ++nt) {
                    int col = cb + nt * 8;
                    float q0 = qs[head * 64 + col];
                    float q1 = qs[head * 64 + col + 1];
                    const float* K = aK[mt][nt];
                    const float* G = aG[mt][nt];
                    p0 += q0 * gatefn(K[0], G[0]);
                    p0 += q1 * gatefn(K[1], G[1]);
                    p1 += q0 * gatefn(K[2], G[2]);
                    p1 += q1 * gatefn(K[3], G[3]);
                }
                p0 += __shfl_xor_sync(0xffffffffu, p0, 1);
                p0 += __shfl_xor_sync(0xffffffffu, p0, 2);
                p1 += __shfl_xor_sync(0xffffffffu, p1, 1);
                p1 += __shfl_xor_sync(0xffffffffu, p1, 2);
                if ((lane & 3) == 0) {
                    int row = warp_m * 64 + mt * 16 + (lane >> 2);
                    spart[warp_n * 128 + row]     = p0;
                    spart[warp_n * 128 + row + 8] = p1;
                }
            }
            __syncthreads();
            {
                int row = tid & 127;
                int hh  = tid >> 7;
                float sc = spart[(2 * hh) * 128 + row] + spart[(2 * hh + 1) * 128 + row];
                g_scores[((size_t)b * H_ + hp * 2 + hh) * N_ + n0 + row] = sc;
            }
            __syncthreads();
        }
    }
}

// ---------------------------------------------------------------------------
__global__ __launch_bounds__(1024)
void pass2a_kernel()
{
    __shared__ float red[32];
    const int bh  = blockIdx.x;
    const int tid = threadIdx.x;
    float* sc = g_scores + (size_t)bh * N_;

    float mx = -1e30f;
    for (int i = tid; i < N_; i += 1024) mx = fmaxf(mx, sc[i]);
#pragma unroll
    for (int off = 16; off >= 1; off >>= 1)
        mx = fmaxf(mx, __shfl_xor_sync(0xffffffffu, mx, off));
    if ((tid & 31) == 0) red[tid >> 5] = mx;
    __syncthreads();
    if (tid < 32) {
        float v = red[tid];
#pragma unroll
        for (int off = 16; off >= 1; off >>= 1)
            v = fmaxf(v, __shfl_xor_sync(0xffffffffu, v, off));
        if (tid == 0) red[0] = v;
    }
    __syncthreads();
    mx = red[0];
    __syncthreads();

    float sum = 0.f;
    for (int i = tid; i < N_; i += 1024) {
        float e = __expf(sc[i] - mx);
        sc[i] = e;
        sum += e;
    }
#pragma unroll
    for (int off = 16; off >= 1; off >>= 1)
        sum += __shfl_xor_sync(0xffffffffu, sum, off);
    if ((tid & 31) == 0) red[tid >> 5] = sum;
    __syncthreads();
    if (tid < 32) {
        float v = red[tid];
#pragma unroll
        for (int off = 16; off >= 1; off >>= 1)
            v += __shfl_xor_sync(0xffffffffu, v, off);
        if (tid == 0) g_inv[bh] = 1.f / v;
    }
}

// grid = 128 bh x 16 chunks of 512 rows
__global__ __launch_bounds__(256)
void pass2b_kernel(const float* __restrict__ x)
{
    __shared__ float red[256];
    const int bh = blockIdx.x >> 4;
    const int ch = blockIdx.x & 15;
    const int b  = bh >> 3;
    const int h  = bh & 7;
    const int tid = threadIdx.x;
    const int d   = tid & 63;
    const int sl  = tid >> 6;

    const float* w  = g_scores + (size_t)bh * N_;
    const float* xp = x + (size_t)b * N_ * D_ + h * DK_ + d;
    const int base = ch * 512;

    float a = 0.f;
    for (int n = base + sl; n < base + 512; n += 16) {
        a = fmaf(w[n],      xp[(size_t)(n)      * D_], a);
        a = fmaf(w[n + 4],  xp[(size_t)(n + 4)  * D_], a);
        a = fmaf(w[n + 8],  xp[(size_t)(n + 8)  * D_], a);
        a = fmaf(w[n + 12], xp[(size_t)(n + 12) * D_], a);
    }
    red[tid] = a;
    __syncthreads();
    if (tid < 64)
        g_partial[((size_t)bh * 16 + ch) * DK_ + tid] =
            (red[tid] + red[tid + 64]) + (red[tid + 128] + red[tid + 192]);
}

__global__ __launch_bounds__(512)
void pass2c_kernel(float* __restrict__ out)
{
    const int b   = blockIdx.x;
    const int col = threadIdx.x;
    const int h   = col >> 6;
    const int d   = col & 63;
    const int bh  = b * 8 + h;
    float s = 0.f;
#pragma unroll
    for (int ch = 0; ch < 16; ++ch)
        s += g_partial[((size_t)bh * 16 + ch) * DK_ + d];
    out[(size_t)b * D_ + col] = s * g_inv[bh];
}

// ---------------------------------------------------------------------------
extern "C" void kernel_launch(void* const* d_in, const int* in_sizes, int n_in,
                              void* d_out, int out_size)
{
    const float* x  = (const float*)d_in[0];
    const float* Wk = (const float*)d_in[1];
    const float* Wg = (const float*)d_in[2];
    const float* q  = (const float*)d_in[3];
    float* out = (float*)d_out;

    cudaFuncSetAttribute(pass1_kernel, cudaFuncAttributeMaxDynamicSharedMemorySize, SMEM_TOTAL);

    cvt_w_kernel<<<1024, 256>>>(Wk, Wg);
    cvt_x_kernel<<<(int)((size_t)ROWS_ * D_ / 1024), 256>>>(x);
    pass1_kernel<<<ROWS_ / 128, 256, SMEM_TOTAL>>>(q);
    pass2a_kernel<<<B_ * H_, 1024>>>();
    pass2b_kernel<<<B_ * H_ * 16, 256>>>(x);
    pass2c_kernel<<<B_, 512>>>(out);
}